// round 17
// baseline (speedup 1.0000x reference)
#include <cuda_runtime.h>
#include <cuda_fp16.h>
#include <stdint.h>

#define B_  4
#define S_  2048
#define D_  1024
#define H_  16
#define M_  (B_*S_)

__device__ __half gxh[(size_t)M_*D_];
__device__ __half gw_f[3u*D_*D_];
__device__ __half gq_f[(size_t)M_*D_];   // pre-scaled by 0.125*log2e
__device__ __half gk_f[(size_t)M_*D_];
__device__ __half gv_f[(size_t)M_*D_];
__device__ float  gmsk[(size_t)B_*S_];   // mask * log2e

__device__ __forceinline__ uint32_t smem_u32(const void* p){
    uint32_t a; asm("{ .reg .u64 t; cvta.to.shared.u64 t, %1; cvt.u32.u64 %0, t; }":"=r"(a):"l"(p)); return a;
}
#define MMAH(d,a,b) asm volatile( \
    "mma.sync.aligned.m16n8k16.row.col.f32.f16.f16.f32 {%0,%1,%2,%3},{%4,%5,%6,%7},{%8,%9},{%0,%1,%2,%3};" \
    : "+f"((d)[0]),"+f"((d)[1]),"+f"((d)[2]),"+f"((d)[3]) \
    : "r"((a)[0]),"r"((a)[1]),"r"((a)[2]),"r"((a)[3]),"r"((b)[0]),"r"((b)[1]))
#define LDM4(r,ad) asm volatile("ldmatrix.sync.aligned.m8n8.x4.shared.b16 {%0,%1,%2,%3},[%4];" \
    : "=r"((r)[0]),"=r"((r)[1]),"=r"((r)[2]),"=r"((r)[3]) : "r"(ad))
#define LDM4T(r,ad) asm volatile("ldmatrix.sync.aligned.m8n8.x4.trans.shared.b16 {%0,%1,%2,%3},[%4];" \
    : "=r"((r)[0]),"=r"((r)[1]),"=r"((r)[2]),"=r"((r)[3]) : "r"(ad))
#define CPA(dst,src) asm volatile("cp.async.cg.shared.global [%0],[%1],16;"::"r"((uint32_t)(dst)),"l"(src):"memory")
#define CPC() asm volatile("cp.async.commit_group;":::"memory")
#define CPW(n) asm volatile("cp.async.wait_group %0;"::"n"(n):"memory")

__device__ __forceinline__ float ex2f(float x){
    float r; asm("ex2.approx.f32 %0, %1;":"=f"(r):"f"(x)); return r;
}
__device__ __forceinline__ uint32_t h2u(float v0, float v1){
    __half2 h = __floats2half2_rn(v0, v1);
    return *(uint32_t*)&h;
}

// ------------- fused conversions: [0,8192)=X, [8192,11264)=W, [11264,11296)=mask -------------
__global__ void conv_all(const float* __restrict__ X,
                         const float* __restrict__ Wq,const float* __restrict__ Wk,const float* __restrict__ Wv,
                         const float* __restrict__ m){
    __shared__ float t[32][33];
    const int bid = blockIdx.x, tid = threadIdx.x;
    if (bid < 8192){
        size_t i = (size_t)bid*256 + tid;
        float4 v = ((const float4*)X)[i];
        ((uint2*)gxh)[i] = make_uint2(h2u(v.x, v.y), h2u(v.z, v.w));
    } else if (bid < 11264){
        int wb = bid - 8192;
        int z = wb >> 10, rem = wb & 1023;
        int n0 = (rem & 31)*32, k0 = (rem >> 5)*32;
        const float* W = (z==0)?Wq:(z==1)?Wk:Wv;
        int lx = tid & 31, ly = tid >> 5;
        for (int i=0;i<4;i++){ int r = ly*4+i; t[r][lx] = W[(size_t)(k0+r)*D_ + n0+lx]; }
        __syncthreads();
        for (int i=0;i<4;i++){
            int nl = ly*4+i;
            gw_f[(size_t)z*D_*D_ + (size_t)(n0+nl)*D_ + k0 + lx] = __float2half_rn(t[lx][nl]);
        }
    } else {
        int i = (bid-11264)*256 + tid;
        gmsk[i] = m[i] * 1.4426950409f;
    }
}

// ------------- QKV projection GEMM (fp16 mma.sync, 5-stage ring, lookahead 3, K=1024) -------------
__global__ void __launch_bounds__(256,2)
qkv_gemm(const float* __restrict__ bq,const float* __restrict__ bk,const float* __restrict__ bv){
    extern __shared__ __align__(16) char smem[];
    uint32_t sb = smem_u32(smem);
    const int tid=threadIdx.x, lane=tid&31, wid=tid>>5;
    const int z=blockIdx.z, n0=blockIdx.x*128, m0=blockIdx.y*128;
    const __half* WF = gw_f + (size_t)z*D_*D_;
    const int wm=(wid>>2)*64, wn=(wid&3)*32;
    float acc[4][4][4];
    #pragma unroll
    for (int a=0;a<4;a++) for (int b2=0;b2<4;b2++) for (int c=0;c<4;c++) acc[a][b2][c]=0.f;

    const int r_ld = tid>>1;
    const int c_ld = (tid&1)*2;
    #define ISSUE(kc) do{ \
        int k0=(kc)*32; \
        uint32_t st = sb + (uint32_t)(((kc)%5)*20480); \
        CPA(st + r_ld*80 + c_ld*16,        gxh + (size_t)(m0+r_ld)*D_ + k0 + c_ld*8); \
        CPA(st + r_ld*80 + (c_ld+1)*16,    gxh + (size_t)(m0+r_ld)*D_ + k0 + c_ld*8 + 8); \
        CPA(st+10240 + r_ld*80 + c_ld*16,     WF + (size_t)(n0+r_ld)*D_ + k0 + c_ld*8); \
        CPA(st+10240 + r_ld*80 + (c_ld+1)*16, WF + (size_t)(n0+r_ld)*D_ + k0 + c_ld*8 + 8); \
        CPC(); }while(0)

    ISSUE(0); ISSUE(1); ISSUE(2);
    const int kr=(lane&7)+((lane>>4)<<3), dof=((lane>>3)&1)*8;
    for (int kc=0;kc<32;kc++){
        if (kc+3<32) ISSUE(kc+3); else CPC();
        CPW(3);
        __syncthreads();
        uint32_t Asm = sb + (uint32_t)((kc%5)*20480), Bsm = Asm+10240;
        #pragma unroll
        for (int ks=0;ks<2;ks++){
            uint32_t a[4][4], bf[2][4];
            #pragma unroll
            for (int tm=0;tm<4;tm++)
                LDM4(a[tm], Asm + (uint32_t)((wm+tm*16+(lane&15))*80 + (ks*16+(lane>>4)*8)*2));
            #pragma unroll
            for (int tp=0;tp<2;tp++)
                LDM4(bf[tp], Bsm + (uint32_t)((wn+tp*16+kr)*80 + (ks*16+dof)*2));
            #pragma unroll
            for (int tm=0;tm<4;tm++)
                #pragma unroll
                for (int tn=0;tn<4;tn++)
                    MMAH(acc[tm][tn], a[tm], &bf[tn>>1][(tn&1)*2]);
        }
    }
    const float* bias=(z==0)?bq:(z==1)?bk:bv;
    __half* gdst = (z==0)?gq_f:(z==1)?gk_f:gv_f;
    const float qs = (z==0)? 0.1803368801f : 1.0f;
    #pragma unroll
    for (int tm=0;tm<4;tm++){
        int r0=m0+wm+tm*16+(lane>>2);
        #pragma unroll
        for (int tn=0;tn<4;tn++){
            int c=n0+wn+tn*8+(lane&3)*2;
            float b0=bias[c], b1=bias[c+1];
            *(uint32_t*)(gdst + (size_t)r0*D_ + c)     = h2u((acc[tm][tn][0]+b0)*qs, (acc[tm][tn][1]+b1)*qs);
            *(uint32_t*)(gdst + (size_t)(r0+8)*D_ + c) = h2u((acc[tm][tn][2]+b0)*qs, (acc[tm][tn][3]+b1)*qs);
        }
    }
}

// ------------- attention (fp16 mma.sync flash, Bc=64, 6-stage ring, 1 bar per 2 kt) -------------
// smem: mask 6x256B @0..1536 | stage s at 2048+s*18432: KF+0 VF+9216 (64 rows x 144B)
__global__ void __launch_bounds__(256,2)
attn_mma(const float* __restrict__ mask, float* __restrict__ out){
    extern __shared__ __align__(16) char smem[];
    uint32_t sb = smem_u32(smem);
    const int tid=threadIdx.x, lane=tid&31, wid=tid>>5;
    const int b=blockIdx.z, h=blockIdx.y, q0=blockIdx.x*128;
    const uint32_t S0 = sb + 2048;

    // stage Q once (fp16, pre-scaled), build A-frags
    #pragma unroll
    for (int i=0;i<4;i++){
        int id=tid+i*256, r=(id>>3)&127, c=id&7;
        CPA(S0 + (uint32_t)(r*144 + c*16), gq_f + (size_t)(b*S_+q0+r)*D_ + h*64 + c*8);
    }
    CPC(); CPW(0); __syncthreads();
    uint32_t aq[4][4];
    #pragma unroll
    for (int kd=0;kd<4;kd++)
        LDM4(aq[kd], S0 + (uint32_t)((wid*16+(lane&15))*144 + (kd*16+(lane>>4)*8)*2));
    __syncthreads();

    #define AISSUE(kt) do{ \
        uint32_t stb = sb + 2048 + (uint32_t)(((kt)%6)*18432); \
        _Pragma("unroll") \
        for (int i=0;i<4;i++){ \
            int id=tid+i*256, mat=id>>9, r=(id>>3)&63, c=id&7; \
            const __half* src = mat? gv_f : gk_f; \
            CPA(stb + (uint32_t)(mat*9216 + r*144 + c*16), src + (size_t)(b*S_+(kt)*64+r)*D_ + h*64 + c*8); \
        } \
        if (tid<16) CPA(sb + ((kt)%6)*256 + tid*16, gmsk + b*S_ + (kt)*64 + tid*4); \
        CPC(); }while(0)

    float o[8][4];
    #pragma unroll
    for (int i=0;i<8;i++) for (int j=0;j<4;j++) o[i][j]=0.f;
    float fl[4];
    #pragma unroll
    for (int j=0;j<4;j++) fl[j]=0.f;
    const uint32_t ones2[2] = {0x3C003C00u, 0x3C003C00u};
    const int kr=(lane&7)+((lane>>4)<<3), dof=((lane>>3)&1)*8;
    const int vr=(lane&7)+(((lane>>3)&1)<<3), vof=(lane>>4)*8;

    AISSUE(0); AISSUE(1);
    for (int kt=0;kt<32;kt+=2){
        if (kt+2<32) AISSUE(kt+2); else CPC();
        if (kt+3<32) AISSUE(kt+3); else CPC();
        CPW(2);
        __syncthreads();
        #pragma unroll
        for (int sub=0;sub<2;sub++){
            const int kti = kt + sub;
            const uint32_t stb = sb + 2048 + (uint32_t)((kti%6)*18432);
            const uint32_t KF=stb, VF=stb+9216;
            const float* msk = (const float*)(smem + (kti%6)*256);

            #pragma unroll
            for (int ck=0;ck<4;ck++){
                float s[2][4];
                #pragma unroll
                for (int i=0;i<2;i++) for (int j=0;j<4;j++) s[i][j]=0.f;
                #pragma unroll
                for (int kd=0;kd<4;kd++){
                    uint32_t bf[4];
                    LDM4(bf, KF + (uint32_t)((ck*16+kr)*144 + (kd*16+dof)*2));
                    MMAH(s[0], aq[kd], bf);
                    MMAH(s[1], aq[kd], bf+2);
                }
                uint32_t ph[4];
                #pragma unroll
                for (int nt=0;nt<2;nt++){
                    int col = ck*16 + nt*8 + (lane&3)*2;
                    float m0f = msk[col], m1f = msk[col+1];
                    float e0 = ex2f(s[nt][0] + m0f);
                    float e1 = ex2f(s[nt][1] + m1f);
                    float e2 = ex2f(s[nt][2] + m0f);
                    float e3 = ex2f(s[nt][3] + m1f);
                    ph[nt*2]   = h2u(e0, e1);
                    ph[nt*2+1] = h2u(e2, e3);
                }
                MMAH(fl, ph, ones2);
                #pragma unroll
                for (int dn=0;dn<4;dn++){
                    uint32_t vb[4];
                    LDM4T(vb, VF + (uint32_t)((ck*16+vr)*144 + (dn*16+vof)*2));
                    MMAH(o[2*dn],   ph, vb);
                    MMAH(o[2*dn+1], ph, vb+2);
                }
            }
        }
    }
    const float i0 = 1.f/fl[0], i1 = 1.f/fl[2];
    const int r0 = q0 + wid*16 + (lane>>2);
    float* op = out + (size_t)(b*S_+r0)*D_ + h*64 + (lane&3)*2;
    #pragma unroll
    for (int dn=0;dn<8;dn++){
        *(float2*)(op + dn*8)        = make_float2(o[dn][0]*i0, o[dn][1]*i0);
        *(float2*)(op + 8*D_ + dn*8) = make_float2(o[dn][2]*i1, o[dn][3]*i1);
    }
}

// ---------------------------------------------------------------------------
extern "C" void kernel_launch(void* const* d_in, const int* in_sizes, int n_in,
                              void* d_out, int out_size)
{
    const float* X    = (const float*)d_in[0];
    const float* mask = (const float*)d_in[1];
    const float* Wq   = (const float*)d_in[2];
    const float* bq   = (const float*)d_in[3];
    const float* Wk   = (const float*)d_in[4];
    const float* bk   = (const float*)d_in[5];
    const float* Wv   = (const float*)d_in[6];
    const float* bv   = (const float*)d_in[7];
    float* out = (float*)d_out;

    cudaFuncSetAttribute(qkv_gemm, cudaFuncAttributeMaxDynamicSharedMemorySize, 102400);
    cudaFuncSetAttribute(attn_mma, cudaFuncAttributeMaxDynamicSharedMemorySize, 112640);

    conv_all<<<11296, 256>>>(X, Wq, Wk, Wv, mask);
    qkv_gemm<<<dim3(8,64,3), 256, 102400>>>(bq, bk, bv);
    attn_mma<<<dim3(16,16,4), 256, 112640>>>(mask, out);
}